// round 1
// baseline (speedup 1.0000x reference)
#include <cuda_runtime.h>

// 3D LUT trilinear interpolation.
// lut: [1,3,33,33,33] f32  (431 KB total, 144 KB per channel)
// x:   [8,3,1024,1024] f32 in [0,1)
// out: [8,3,1024,1024] f32
//
// Strategy: blockIdx.y = output channel. Each CTA stages that channel's
// 33^3 LUT slice into shared memory (143748 B -> 1 CTA/SM), then
// grid-strides over pixels with float4-vectorized loads of the three
// x planes, doing 8 random LDS.32 taps per pixel.

#define LUT_D  33
#define LUT_D2 (33 * 33)
#define LUT_D3 (33 * 33 * 33)
#define HW     (1024 * 1024)
#define NBATCH 8
#define NPIX   (NBATCH * HW)          // 8388608 pixels
#define SMEM_BYTES (LUT_D3 * 4)       // 143748

__device__ __forceinline__ float lut_interp1(const float* __restrict__ slut,
                                             float r, float g, float b)
{
    // v in [0, 32]
    float vr = __saturatef(r) * 32.0f;
    float vg = __saturatef(g) * 32.0f;
    float vb = __saturatef(b) * 32.0f;

    float fr0 = floorf(vr), fg0 = floorf(vg), fb0 = floorf(vb);
    int ir = (int)fr0, ig = (int)fg0, ib = (int)fb0;
    float fr = vr - fr0, fg = vg - fg0, fb = vb - fb0;

    // i1 = min(i0+1, 32) expressed as delta offsets (0 when at the edge)
    int dr = (ir < LUT_D - 1) ? LUT_D2 : 0;
    int dg = (ig < LUT_D - 1) ? LUT_D  : 0;
    int db = (ib < LUT_D - 1) ? 1      : 0;

    int base = ir * LUT_D2 + ig * LUT_D + ib;

    float c000 = slut[base];
    float c001 = slut[base + db];
    float c010 = slut[base + dg];
    float c011 = slut[base + dg + db];
    float c100 = slut[base + dr];
    float c101 = slut[base + dr + db];
    float c110 = slut[base + dr + dg];
    float c111 = slut[base + dr + dg + db];

    // lerp tree: b innermost, then g, then r
    float c00 = fmaf(fb, c001 - c000, c000);
    float c01 = fmaf(fb, c011 - c010, c010);
    float c10 = fmaf(fb, c101 - c100, c100);
    float c11 = fmaf(fb, c111 - c110, c110);
    float c0  = fmaf(fg, c01 - c00, c00);
    float c1  = fmaf(fg, c11 - c10, c10);
    return fmaf(fr, c1 - c0, c0);
}

__global__ __launch_bounds__(1024, 1)
void TrilinearInterpolation_82171314307385_kernel(const float* __restrict__ lut,
                                                  const float* __restrict__ x,
                                                  float* __restrict__ out)
{
    extern __shared__ float slut[];
    const int c = blockIdx.y;  // output channel 0..2

    // Stage this channel's LUT slice into shared memory (coalesced).
    const float* lutc = lut + c * LUT_D3;
    for (int i = threadIdx.x; i < LUT_D3; i += blockDim.x)
        slut[i] = lutc[i];
    __syncthreads();

    const int n4 = NPIX / 4;  // float4 pixel groups
    const int stride = gridDim.x * blockDim.x;

    for (int idx = blockIdx.x * blockDim.x + threadIdx.x; idx < n4; idx += stride) {
        int p  = idx << 2;          // first pixel of this group
        int b  = p >> 20;           // batch index (HW = 1<<20)
        int hw = p & (HW - 1);

        const float* xb0 = x + (size_t)(b * 3) * HW + hw;
        float4 xr = *(const float4*)(xb0);
        float4 xg = *(const float4*)(xb0 + HW);
        float4 xb = *(const float4*)(xb0 + 2 * HW);

        float4 o;
        o.x = lut_interp1(slut, xr.x, xg.x, xb.x);
        o.y = lut_interp1(slut, xr.y, xg.y, xb.y);
        o.z = lut_interp1(slut, xr.z, xg.z, xb.z);
        o.w = lut_interp1(slut, xr.w, xg.w, xb.w);

        *(float4*)(out + (size_t)(b * 3 + c) * HW + hw) = o;
    }
}

extern "C" void kernel_launch(void* const* d_in, const int* in_sizes, int n_in,
                              void* d_out, int out_size)
{
    const float* lut = (const float*)d_in[0];   // [1,3,33,33,33]
    const float* x   = (const float*)d_in[1];   // [8,3,1024,1024]
    float* out       = (float*)d_out;           // [8,3,1024,1024]

    (void)in_sizes; (void)n_in; (void)out_size;

    cudaFuncSetAttribute(TrilinearInterpolation_82171314307385_kernel,
                         cudaFuncAttributeMaxDynamicSharedMemorySize, SMEM_BYTES);

    dim3 grid(148, 3);   // 148 CTAs (1/SM at this smem footprint) x 3 channels
    TrilinearInterpolation_82171314307385_kernel<<<grid, 1024, SMEM_BYTES>>>(lut, x, out);
}

// round 2
// speedup vs baseline: 1.4759x; 1.4759x over previous
#include <cuda_runtime.h>
#include <cuda_fp16.h>

// 3D LUT trilinear interpolation — round 2.
// lut: [1,3,33,33,33] f32 ; x: [8,3,1024,1024] f32 in [0,1) ; out: same as x.
//
// R1 evidence: L1tex pipe 79% (8 random LDS.32/pixel-channel), DRAM 43%
// (x streamed 3x). This round:
//  (a) smem LUT stored as half2 b-pairs -> 4 LDS per pixel-channel (was 8)
//  (b) 1D grid, channel = bid%3, region = bid/3: the 3 channel-siblings of a
//      region are co-resident in the same wave and share x through L2,
//      removing the 3x DRAM re-read.

#define LUT_D  33
#define LUT_D2 (33 * 33)
#define LUT_D3 (33 * 33 * 33)      // 35937
#define HW     (1024 * 1024)
#define NBATCH 8
#define NPIX   (NBATCH * HW)       // 8388608
#define NGROUPS (NPIX / 4)         // float4 groups: 2097152
#define NREGION 148
#define SMEM_BYTES (LUT_D3 * 4)    // 143748 B of half2 pairs

__device__ __forceinline__ float lut_interp_pair(const half2* __restrict__ slut,
                                                 float r, float g, float b)
{
    float vr = __saturatef(r) * 32.0f;
    float vg = __saturatef(g) * 32.0f;
    float vb = __saturatef(b) * 32.0f;

    // floor via cast (v >= 0); clamp to 31 so the +1 neighbor is always valid.
    int ir = min((int)vr, LUT_D - 2);
    int ig = min((int)vg, LUT_D - 2);
    int ib = min((int)vb, LUT_D - 2);
    float fr = vr - (float)ir;
    float fg = vg - (float)ig;
    float fb = vb - (float)ib;

    int base = ir * LUT_D2 + ig * LUT_D + ib;

    // Each pair load gives (c[b], c[b+1]) for one (r,g) corner.
    half2 p00 = slut[base];
    half2 p01 = slut[base + LUT_D];
    half2 p10 = slut[base + LUT_D2];
    half2 p11 = slut[base + LUT_D2 + LUT_D];

    float2 a00 = __half22float2(p00);
    float2 a01 = __half22float2(p01);
    float2 a10 = __half22float2(p10);
    float2 a11 = __half22float2(p11);

    float c00 = fmaf(fb, a00.y - a00.x, a00.x);
    float c01 = fmaf(fb, a01.y - a01.x, a01.x);
    float c10 = fmaf(fb, a10.y - a10.x, a10.x);
    float c11 = fmaf(fb, a11.y - a11.x, a11.x);

    float c0 = fmaf(fg, c01 - c00, c00);
    float c1 = fmaf(fg, c11 - c10, c10);
    return fmaf(fr, c1 - c0, c0);
}

__global__ __launch_bounds__(1024, 1)
void TrilinearInterpolation_82171314307385_kernel(const float* __restrict__ lut,
                                                  const float* __restrict__ x,
                                                  float* __restrict__ out)
{
    extern __shared__ half2 slut[];

    const int c      = blockIdx.x % 3;        // output channel
    const int region = blockIdx.x / 3;        // x-slice; siblings share it via L2

    // Stage this channel's LUT as half2 (c[i], c[i+1]) pairs.
    const float* lutc = lut + c * LUT_D3;
    for (int i = threadIdx.x; i < LUT_D3; i += blockDim.x) {
        float a0 = lutc[i];
        float a1 = lutc[min(i + 1, LUT_D3 - 1)];
        slut[i] = __floats2half2_rn(a0, a1);
    }
    __syncthreads();

    // Static contiguous partition of float4 groups across regions.
    const int start = (int)(((long long)region * NGROUPS) / NREGION);
    const int end   = (int)(((long long)(region + 1) * NGROUPS) / NREGION);

    for (int idx = start + (int)threadIdx.x; idx < end; idx += 1024) {
        int p  = idx << 2;
        int bi = p >> 20;            // batch (HW = 1<<20)
        int hw = p & (HW - 1);

        const float* xb0 = x + (size_t)(bi * 3) * HW + hw;
        float4 xr = *(const float4*)(xb0);
        float4 xg = *(const float4*)(xb0 + HW);
        float4 xb = *(const float4*)(xb0 + 2 * HW);

        float4 o;
        o.x = lut_interp_pair(slut, xr.x, xg.x, xb.x);
        o.y = lut_interp_pair(slut, xr.y, xg.y, xb.y);
        o.z = lut_interp_pair(slut, xr.z, xg.z, xb.z);
        o.w = lut_interp_pair(slut, xr.w, xg.w, xb.w);

        *(float4*)(out + (size_t)(bi * 3 + c) * HW + hw) = o;
    }
}

extern "C" void kernel_launch(void* const* d_in, const int* in_sizes, int n_in,
                              void* d_out, int out_size)
{
    const float* lut = (const float*)d_in[0];
    const float* x   = (const float*)d_in[1];
    float* out       = (float*)d_out;
    (void)in_sizes; (void)n_in; (void)out_size;

    cudaFuncSetAttribute(TrilinearInterpolation_82171314307385_kernel,
                         cudaFuncAttributeMaxDynamicSharedMemorySize, SMEM_BYTES);

    TrilinearInterpolation_82171314307385_kernel<<<3 * NREGION, 1024, SMEM_BYTES>>>(lut, x, out);
}

// round 7
// speedup vs baseline: 1.5527x; 1.0521x over previous
#include <cuda_runtime.h>
#include <cuda_fp16.h>

// 3D LUT trilinear interpolation — round 3.
// R2 evidence: L1tex 74.3% (not saturated), issue 56.9%, DRAM 27.6% (fine).
// 32 warps/SM can't cover the LDG latency at each iteration head.
// This round: software prefetch of next iteration's x float4s so LDG
// long-scoreboard overlaps the current group's 16 LDS + FMA tree.

#define LUT_D  33
#define LUT_D2 (33 * 33)
#define LUT_D3 (33 * 33 * 33)      // 35937
#define HW     (1024 * 1024)
#define NBATCH 8
#define NPIX   (NBATCH * HW)       // 8388608
#define NGROUPS (NPIX / 4)         // 2097152 float4 groups
#define NREGION 148
#define SMEM_BYTES (LUT_D3 * 4)    // 143748 B of half2 b-pairs

__device__ __forceinline__ float lut_interp_pair(const half2* __restrict__ slut,
                                                 float r, float g, float b)
{
    float vr = __saturatef(r) * 32.0f;
    float vg = __saturatef(g) * 32.0f;
    float vb = __saturatef(b) * 32.0f;

    int ir = min((int)vr, LUT_D - 2);
    int ig = min((int)vg, LUT_D - 2);
    int ib = min((int)vb, LUT_D - 2);
    float fr = vr - (float)ir;
    float fg = vg - (float)ig;
    float fb = vb - (float)ib;

    int base = ir * LUT_D2 + ig * LUT_D + ib;

    half2 p00 = slut[base];
    half2 p01 = slut[base + LUT_D];
    half2 p10 = slut[base + LUT_D2];
    half2 p11 = slut[base + LUT_D2 + LUT_D];

    float2 a00 = __half22float2(p00);
    float2 a01 = __half22float2(p01);
    float2 a10 = __half22float2(p10);
    float2 a11 = __half22float2(p11);

    float c00 = fmaf(fb, a00.y - a00.x, a00.x);
    float c01 = fmaf(fb, a01.y - a01.x, a01.x);
    float c10 = fmaf(fb, a10.y - a10.x, a10.x);
    float c11 = fmaf(fb, a11.y - a11.x, a11.x);

    float c0 = fmaf(fg, c01 - c00, c00);
    float c1 = fmaf(fg, c11 - c10, c10);
    return fmaf(fr, c1 - c0, c0);
}

__global__ __launch_bounds__(1024, 1)
void TrilinearInterpolation_82171314307385_kernel(const float* __restrict__ lut,
                                                  const float* __restrict__ x,
                                                  float* __restrict__ out)
{
    extern __shared__ half2 slut[];

    const int c      = blockIdx.x % 3;
    const int region = blockIdx.x / 3;

    const float* lutc = lut + c * LUT_D3;
    for (int i = threadIdx.x; i < LUT_D3; i += blockDim.x) {
        float a0 = lutc[i];
        float a1 = lutc[min(i + 1, LUT_D3 - 1)];
        slut[i] = __floats2half2_rn(a0, a1);
    }
    __syncthreads();

    const int start = (int)(((long long)region * NGROUPS) / NREGION);
    const int end   = (int)(((long long)(region + 1) * NGROUPS) / NREGION);

    int idx = start + (int)threadIdx.x;
    if (idx >= end) return;

    // --- prologue: load first group ---
    int p  = idx << 2;
    int bi = p >> 20;
    int hw = p & (HW - 1);
    const float* xb0 = x + (size_t)(bi * 3) * HW + hw;
    float4 xr = *(const float4*)(xb0);
    float4 xg = *(const float4*)(xb0 + HW);
    float4 xb = *(const float4*)(xb0 + 2 * HW);

    while (true) {
        int nidx = idx + 1024;
        float4 nr, ng, nb;
        bool have_next = (nidx < end);
        if (have_next) {
            // Prefetch next group's x BEFORE the dependent LDS/FMA work so the
            // LDG long-scoreboard drains behind it.
            int np  = nidx << 2;
            int nbi = np >> 20;
            int nhw = np & (HW - 1);
            const float* nxb0 = x + (size_t)(nbi * 3) * HW + nhw;
            nr = *(const float4*)(nxb0);
            ng = *(const float4*)(nxb0 + HW);
            nb = *(const float4*)(nxb0 + 2 * HW);
        }

        float4 o;
        o.x = lut_interp_pair(slut, xr.x, xg.x, xb.x);
        o.y = lut_interp_pair(slut, xr.y, xg.y, xb.y);
        o.z = lut_interp_pair(slut, xr.z, xg.z, xb.z);
        o.w = lut_interp_pair(slut, xr.w, xg.w, xb.w);

        *(float4*)(out + (size_t)(bi * 3 + c) * HW + hw) = o;

        if (!have_next) break;
        idx = nidx;
        p  = idx << 2;
        bi = p >> 20;
        hw = p & (HW - 1);
        xr = nr; xg = ng; xb = nb;
    }
}

extern "C" void kernel_launch(void* const* d_in, const int* in_sizes, int n_in,
                              void* d_out, int out_size)
{
    const float* lut = (const float*)d_in[0];
    const float* x   = (const float*)d_in[1];
    float* out       = (float*)d_out;
    (void)in_sizes; (void)n_in; (void)out_size;

    cudaFuncSetAttribute(TrilinearInterpolation_82171314307385_kernel,
                         cudaFuncAttributeMaxDynamicSharedMemorySize, SMEM_BYTES);

    TrilinearInterpolation_82171314307385_kernel<<<3 * NREGION, 1024, SMEM_BYTES>>>(lut, x, out);
}